// round 7
// baseline (speedup 1.0000x reference)
#include <cuda_runtime.h>
#include <cuda_bf16.h>
#include <math.h>
#include <stdint.h>

#define BB 4
#define HH 16
#define SSEQ 1024
#define DKD 64
#define TQ 64
#define NT 256
#define NEGV (-1.0e9f)
#define PADB 144            // bf16 row: 128B padded to 144B -> conflict-free ldmatrix

#define OFF_QHI 0
#define OFF_QLO 9216
#define OFF_K   18432
#define KSTAGE  36864       // one stage: Khi(18432) + Klo(18432)
#define OFF_RED (OFF_K + 2 * KSTAGE)          // 92160
#define SMEM_TOTAL (OFF_RED + (128 + 64) * 4) // 92928 B -> occ 2

#define NELEM (BB * HH * SSEQ * DKD)          // 4,194,304

__device__ __nv_bfloat16 gQhi[NELEM];
__device__ __nv_bfloat16 gQlo[NELEM];
__device__ __nv_bfloat16 gKhi[NELEM];
__device__ __nv_bfloat16 gKlo[NELEM];

__device__ __forceinline__ uint32_t smem_u32(const void* p) {
    uint32_t a;
    asm("{ .reg .u64 t; cvta.to.shared.u64 t, %1; cvt.u32.u64 %0, t; }" : "=r"(a) : "l"(p));
    return a;
}
__device__ __forceinline__ uint32_t pack_bf2(__nv_bfloat16 a, __nv_bfloat16 b) {
    return (uint32_t)__bfloat16_as_ushort(a) | ((uint32_t)__bfloat16_as_ushort(b) << 16);
}
__device__ __forceinline__ void mma_bf16(float* d,
                                         uint32_t a0, uint32_t a1, uint32_t a2, uint32_t a3,
                                         uint32_t b0, uint32_t b1) {
    asm volatile(
        "mma.sync.aligned.m16n8k16.row.col.f32.bf16.bf16.f32 "
        "{%0,%1,%2,%3}, {%4,%5,%6,%7}, {%8,%9}, {%0,%1,%2,%3};"
        : "+f"(d[0]), "+f"(d[1]), "+f"(d[2]), "+f"(d[3])
        : "r"(a0), "r"(a1), "r"(a2), "r"(a3), "r"(b0), "r"(b1));
}
#define LDSM4(r0, r1, r2, r3, a) \
    asm volatile("ldmatrix.sync.aligned.m8n8.x4.shared.b16 {%0,%1,%2,%3}, [%4];" \
                 : "=r"(r0), "=r"(r1), "=r"(r2), "=r"(r3) : "r"(a))
#define CP16(dst, src) \
    asm volatile("cp.async.cg.shared.global [%0], [%1], 16;" :: "r"(dst), "l"(src) : "memory")

// ---- pre-pass: fp32 -> bf16 hi/lo (Q pre-scaled by 0.125) ----
__global__ void __launch_bounds__(256, 8)
cvt_kernel(const float* __restrict__ Q, const float* __restrict__ K)
{
    size_t i = (size_t)blockIdx.x * 256 + threadIdx.x;   // float4 index, 2M total
    bool isQ = i < (NELEM / 4);
    size_t j = isQ ? i : i - (NELEM / 4);
    const float4 v0 = reinterpret_cast<const float4*>(isQ ? Q : K)[j];
    float4 v = v0;
    if (isQ) { v.x *= 0.125f; v.y *= 0.125f; v.z *= 0.125f; v.w *= 0.125f; }
    __nv_bfloat16 bx = __float2bfloat16_rn(v.x), by = __float2bfloat16_rn(v.y);
    __nv_bfloat16 bz = __float2bfloat16_rn(v.z), bw = __float2bfloat16_rn(v.w);
    uint2 hi = make_uint2(pack_bf2(bx, by), pack_bf2(bz, bw));
    uint2 lo = make_uint2(
        pack_bf2(__float2bfloat16_rn(v.x - __bfloat162float(bx)),
                 __float2bfloat16_rn(v.y - __bfloat162float(by))),
        pack_bf2(__float2bfloat16_rn(v.z - __bfloat162float(bz)),
                 __float2bfloat16_rn(v.w - __bfloat162float(bw))));
    if (isQ) {
        reinterpret_cast<uint2*>(gQhi)[j] = hi;
        reinterpret_cast<uint2*>(gQlo)[j] = lo;
    } else {
        reinterpret_cast<uint2*>(gKhi)[j] = hi;
        reinterpret_cast<uint2*>(gKlo)[j] = lo;
    }
}

__global__ void __launch_bounds__(NT, 2)
mha_fused(const int* __restrict__ M,
          float* __restrict__ attn, float* __restrict__ scores)
{
    extern __shared__ char sm[];
    float* sred = (float*)(sm + OFF_RED);
    float* sinv = sred + 128;

    const int tid  = threadIdx.x;
    const int lane = tid & 31;
    const int wid  = tid >> 5;
    const int wq   = wid >> 1;
    const int wk   = wid & 1;
    const int qt = blockIdx.x, h = blockIdx.y, b = blockIdx.z;
    const int q0 = qt * TQ;

    const size_t qbase = ((size_t)(b * HH + h) * SSEQ + q0) * DKD;
    const size_t kbase = (size_t)(b * HH + h) * SSEQ * DKD;
    const int*   Mp = M + ((size_t)b * SSEQ + q0) * SSEQ;
    float*       Sp = scores + ((size_t)(b * HH + h) * SSEQ + q0) * SSEQ;
    float*       Ap = attn   + ((size_t)(b * HH + h) * SSEQ + q0) * SSEQ;

    const uint32_t sq = smem_u32(sm);
    const uint32_t sk = sq + OFF_K;

    // ---- prologue group 0: Q tiles (hi+lo) + K tile 0 ----
    #pragma unroll
    for (int i = 0; i < 4; i++) {           // Q: 1024 x 16B chunks
        int idx = tid + i * NT;
        int half = idx >> 9, r = (idx >> 3) & 63, c = idx & 7;
        const __nv_bfloat16* src = (half ? gQlo : gQhi) + qbase + (size_t)r * DKD + c * 8;
        CP16(sq + (uint32_t)(half * OFF_QLO + r * PADB + c * 16), src);
    }
    #pragma unroll
    for (int i = 0; i < 8; i++) {           // K tile 0: 2048 x 16B chunks
        int idx = tid + i * NT;
        int half = idx >> 10, r = (idx >> 3) & 127, c = idx & 7;
        const __nv_bfloat16* src = (half ? gKlo : gKhi) + kbase + (size_t)r * DKD + c * 8;
        CP16(sk + (uint32_t)(half * 18432 + r * PADB + c * 16), src);
    }
    asm volatile("cp.async.commit_group;" ::: "memory");
    // ---- group 1: K tile 1 ----
    #pragma unroll
    for (int i = 0; i < 8; i++) {
        int idx = tid + i * NT;
        int half = idx >> 10, r = (idx >> 3) & 127, c = idx & 7;
        const __nv_bfloat16* src = (half ? gKlo : gKhi) + kbase + (size_t)(128 + r) * DKD + c * 8;
        CP16(sk + (uint32_t)(KSTAGE + half * 18432 + r * PADB + c * 16), src);
    }
    asm volatile("cp.async.commit_group;" ::: "memory");

    // ldmatrix per-lane addresses
    const uint32_t aHi = sq + (uint32_t)((wq * 16 + (lane & 15)) * PADB + (lane >> 4) * 16);
    const uint32_t aLo = aHi + OFF_QLO;
    const int rowB = wk * 64 + (lane & 7) + (lane >> 4) * 8;
    const uint32_t bBase = sk + (uint32_t)(rowB * PADB + ((lane >> 3) & 1) * 16);

    const int r0l = wq * 16 + (lane >> 2);
    float sumE0 = 0.0f, sumE1 = 0.0f;

    for (int t = 0; t < SSEQ / 128; t++) {
        const int kt = t * 128;
        asm volatile("cp.async.wait_group 1;" ::: "memory");
        __syncthreads();                     // tile t resident in stage t&1

        const uint32_t bHi = bBase + (uint32_t)((t & 1) * KSTAGE);
        const uint32_t bLo = bHi + 18432;

        float acc[8][4];
        #pragma unroll
        for (int n = 0; n < 8; n++)
            #pragma unroll
            for (int j = 0; j < 4; j++) acc[n][j] = 0.0f;

        #pragma unroll
        for (int s = 0; s < 4; s++) {
            uint32_t ah0, ah1, ah2, ah3, al0, al1, al2, al3;
            LDSM4(ah0, ah1, ah2, ah3, aHi + s * 32);
            LDSM4(al0, al1, al2, al3, aLo + s * 32);
            #pragma unroll
            for (int p = 0; p < 4; p++) {
                uint32_t bh0, bh1, bh2, bh3, bl0, bl1, bl2, bl3;
                LDSM4(bh0, bh1, bh2, bh3, bHi + (uint32_t)(p * 16 * PADB + s * 32));
                LDSM4(bl0, bl1, bl2, bl3, bLo + (uint32_t)(p * 16 * PADB + s * 32));
                mma_bf16(acc[2 * p],     ah0, ah1, ah2, ah3, bh0, bh1);
                mma_bf16(acc[2 * p],     ah0, ah1, ah2, ah3, bl0, bl1);
                mma_bf16(acc[2 * p],     al0, al1, al2, al3, bh0, bh1);
                mma_bf16(acc[2 * p + 1], ah0, ah1, ah2, ah3, bh2, bh3);
                mma_bf16(acc[2 * p + 1], ah0, ah1, ah2, ah3, bl2, bl3);
                mma_bf16(acc[2 * p + 1], al0, al1, al2, al3, bh2, bh3);
            }
        }
        __syncthreads();                     // all warps done reading stage t&1

        // ---- prefetch tile t+2 into stage t&1 (overlaps epilogue) ----
        if (t + 2 < SSEQ / 128) {
            #pragma unroll
            for (int i = 0; i < 8; i++) {
                int idx = tid + i * NT;
                int half = idx >> 10, r = (idx >> 3) & 127, c = idx & 7;
                const __nv_bfloat16* src =
                    (half ? gKlo : gKhi) + kbase + (size_t)(kt + 256 + r) * DKD + c * 8;
                CP16(sk + (uint32_t)((t & 1) * KSTAGE + half * 18432 + r * PADB + c * 16), src);
            }
        }
        asm volatile("cp.async.commit_group;" ::: "memory");

        // ---- epilogue: mask, write scores, accumulate exp sums ----
        #pragma unroll
        for (int nt = 0; nt < 8; nt++) {
            int kc = kt + wk * 64 + nt * 8 + 2 * (lane & 3);
            int2 m0 = *reinterpret_cast<const int2*>(Mp + (size_t)r0l * SSEQ + kc);
            int2 m1 = *reinterpret_cast<const int2*>(Mp + (size_t)(r0l + 8) * SSEQ + kc);
            float s0 = m0.x ? acc[nt][0] : NEGV;
            float s1 = m0.y ? acc[nt][1] : NEGV;
            float s2 = m1.x ? acc[nt][2] : NEGV;
            float s3 = m1.y ? acc[nt][3] : NEGV;
            sumE0 += __expf(s0) + __expf(s1);
            sumE1 += __expf(s2) + __expf(s3);
            *reinterpret_cast<float2*>(Sp + (size_t)r0l * SSEQ + kc)       = make_float2(s0, s1);
            *reinterpret_cast<float2*>(Sp + (size_t)(r0l + 8) * SSEQ + kc) = make_float2(s2, s3);
        }
    }

    // ---- row-sum reduce ----
    sumE0 += __shfl_xor_sync(0xFFFFFFFFu, sumE0, 1);
    sumE0 += __shfl_xor_sync(0xFFFFFFFFu, sumE0, 2);
    sumE1 += __shfl_xor_sync(0xFFFFFFFFu, sumE1, 1);
    sumE1 += __shfl_xor_sync(0xFFFFFFFFu, sumE1, 2);
    if ((lane & 3) == 0) {
        sred[wk * 64 + r0l]     = sumE0;
        sred[wk * 64 + r0l + 8] = sumE1;
    }
    __syncthreads();
    if (tid < 64) sinv[tid] = 1.0f / (sred[tid] + sred[64 + tid]);
    __syncthreads();

    // ---- fused attn pass: re-read scores (L2-hot), normalize ----
    #pragma unroll 8
    for (int i = 0; i < 64; i++) {
        int idx = tid + i * NT;
        float inv = sinv[idx >> 8];
        float4 s = reinterpret_cast<const float4*>(Sp)[idx];
        float4 a;
        a.x = __expf(s.x) * inv;
        a.y = __expf(s.y) * inv;
        a.z = __expf(s.z) * inv;
        a.w = __expf(s.w) * inv;
        reinterpret_cast<float4*>(Ap)[idx] = a;
    }
}

extern "C" void kernel_launch(void* const* d_in, const int* in_sizes, int n_in,
                              void* d_out, int out_size)
{
    const float* Q = (const float*)d_in[0];
    const float* K = (const float*)d_in[1];
    const int*   M = (const int*)d_in[3];    // d_in[2] = value, unused by outputs

    float* attn   = (float*)d_out;
    float* scores = (float*)d_out + (size_t)BB * HH * SSEQ * SSEQ;

    cvt_kernel<<<(2 * NELEM / 4) / 256, 256>>>(Q, K);

    cudaFuncSetAttribute(mha_fused, cudaFuncAttributeMaxDynamicSharedMemorySize, SMEM_TOTAL);
    dim3 grid(SSEQ / TQ, HH, BB);            // 1024 CTAs
    mha_fused<<<grid, NT, SMEM_TOTAL>>>(M, attn, scores);
}

// round 8
// speedup vs baseline: 1.1227x; 1.1227x over previous
#include <cuda_runtime.h>
#include <cuda_bf16.h>
#include <math.h>
#include <stdint.h>

#define BB 4
#define HH 16
#define SSEQ 1024
#define DKD 64
#define TQ 64
#define NT 256
#define NEGV (-1.0e9f)
#define PADB 144

#define OFF_QHI 0
#define OFF_QLO 9216
#define OFF_K   18432
#define KSTAGE  36864
#define OFF_RED (OFF_K + 2 * KSTAGE)
#define SMEM_TOTAL (OFF_RED + (128 + 64) * 4)

#define NELEM (BB * HH * SSEQ * DKD)
#define NMASK (BB * SSEQ * SSEQ)
#define CVT_BLOCKS ((2 * NELEM / 4) / 256)     // 8192
#define MSK_BLOCKS ((NMASK / 16) / 256)        // 1024

__device__ __nv_bfloat16 gQhi[NELEM];
__device__ __nv_bfloat16 gQlo[NELEM];
__device__ __nv_bfloat16 gKhi[NELEM];
__device__ __nv_bfloat16 gKlo[NELEM];
__device__ __align__(16) uint8_t gMB[NMASK];   // fragment-ordered byte mask

__device__ __forceinline__ uint32_t smem_u32(const void* p) {
    uint32_t a;
    asm("{ .reg .u64 t; cvta.to.shared.u64 t, %1; cvt.u32.u64 %0, t; }" : "=r"(a) : "l"(p));
    return a;
}
__device__ __forceinline__ uint32_t pack_bf2(__nv_bfloat16 a, __nv_bfloat16 b) {
    return (uint32_t)__bfloat16_as_ushort(a) | ((uint32_t)__bfloat16_as_ushort(b) << 16);
}
__device__ __forceinline__ void mma_bf16(float* d,
                                         uint32_t a0, uint32_t a1, uint32_t a2, uint32_t a3,
                                         uint32_t b0, uint32_t b1) {
    asm volatile(
        "mma.sync.aligned.m16n8k16.row.col.f32.bf16.bf16.f32 "
        "{%0,%1,%2,%3}, {%4,%5,%6,%7}, {%8,%9}, {%0,%1,%2,%3};"
        : "+f"(d[0]), "+f"(d[1]), "+f"(d[2]), "+f"(d[3])
        : "r"(a0), "r"(a1), "r"(a2), "r"(a3), "r"(b0), "r"(b1));
}
#define LDSM4(r0, r1, r2, r3, a) \
    asm volatile("ldmatrix.sync.aligned.m8n8.x4.shared.b16 {%0,%1,%2,%3}, [%4];" \
                 : "=r"(r0), "=r"(r1), "=r"(r2), "=r"(r3) : "r"(a))
#define CP16(dst, src) \
    asm volatile("cp.async.cg.shared.global [%0], [%1], 16;" :: "r"(dst), "l"(src) : "memory")

// ---- combined pre-pass: bf16 hi/lo conversion + mask byte-packing ----
// Mask packing: within each 128-col tile, out byte [half*64 + e*16 + nt*2 + u]
// = (mask[half*64 + nt*8 + 2e + u] != 0), so the epilogue reads one uint4 per row.
__global__ void __launch_bounds__(256, 8)
prep_kernel(const float* __restrict__ Q, const float* __restrict__ K,
            const int* __restrict__ M)
{
    if (blockIdx.x < CVT_BLOCKS) {
        size_t i = (size_t)blockIdx.x * 256 + threadIdx.x;
        bool isQ = i < (NELEM / 4);
        size_t j = isQ ? i : i - (NELEM / 4);
        float4 v = reinterpret_cast<const float4*>(isQ ? Q : K)[j];
        if (isQ) { v.x *= 0.125f; v.y *= 0.125f; v.z *= 0.125f; v.w *= 0.125f; }
        __nv_bfloat16 bx = __float2bfloat16_rn(v.x), by = __float2bfloat16_rn(v.y);
        __nv_bfloat16 bz = __float2bfloat16_rn(v.z), bw = __float2bfloat16_rn(v.w);
        uint2 hi = make_uint2(pack_bf2(bx, by), pack_bf2(bz, bw));
        uint2 lo = make_uint2(
            pack_bf2(__float2bfloat16_rn(v.x - __bfloat162float(bx)),
                     __float2bfloat16_rn(v.y - __bfloat162float(by))),
            pack_bf2(__float2bfloat16_rn(v.z - __bfloat162float(bz)),
                     __float2bfloat16_rn(v.w - __bfloat162float(bw))));
        if (isQ) { reinterpret_cast<uint2*>(gQhi)[j] = hi; reinterpret_cast<uint2*>(gQlo)[j] = lo; }
        else     { reinterpret_cast<uint2*>(gKhi)[j] = hi; reinterpret_cast<uint2*>(gKlo)[j] = lo; }
    } else {
        // one thread per 16 output bytes (fixed tile, half, e; all nt,u)
        int t = (blockIdx.x - CVT_BLOCKS) * 256 + threadIdx.x;   // 262144
        int tile = t >> 3;
        int w = t & 7;                   // half*4 + e
        int half = w >> 2, e = w & 3;
        const int* src = M + (size_t)tile * 128 + half * 64 + 2 * e;
        uint32_t words[4];
        #pragma unroll
        for (int p = 0; p < 4; p++) {    // word p covers nt=2p, 2p+1
            int2 v0 = *reinterpret_cast<const int2*>(src + (2 * p) * 8);
            int2 v1 = *reinterpret_cast<const int2*>(src + (2 * p + 1) * 8);
            words[p] = (v0.x ? 1u : 0u) | (v0.y ? 0x100u : 0u)
                     | (v1.x ? 0x10000u : 0u) | (v1.y ? 0x1000000u : 0u);
        }
        *reinterpret_cast<uint4*>(gMB + (size_t)tile * 128 + w * 16) =
            make_uint4(words[0], words[1], words[2], words[3]);
    }
}

__global__ void __launch_bounds__(NT, 2)
mha_fused(float* __restrict__ attn, float* __restrict__ scores)
{
    extern __shared__ char sm[];
    float* sred = (float*)(sm + OFF_RED);
    float* sinv = sred + 128;

    const int tid  = threadIdx.x;
    const int lane = tid & 31;
    const int wid  = tid >> 5;
    const int wq   = wid >> 1;
    const int wk   = wid & 1;
    const int qt = blockIdx.x, h = blockIdx.y, b = blockIdx.z;
    const int q0 = qt * TQ;

    const size_t qbase = ((size_t)(b * HH + h) * SSEQ + q0) * DKD;
    const size_t kbase = (size_t)(b * HH + h) * SSEQ * DKD;
    const uint8_t* Mb = gMB + ((size_t)b * SSEQ + q0) * SSEQ;
    float* Sp = scores + ((size_t)(b * HH + h) * SSEQ + q0) * SSEQ;
    float* Ap = attn   + ((size_t)(b * HH + h) * SSEQ + q0) * SSEQ;

    const uint32_t sq = smem_u32(sm);
    const uint32_t sk = sq + OFF_K;

    // ---- prologue group 0: Q (hi+lo) + K tile 0 ----
    #pragma unroll
    for (int i = 0; i < 4; i++) {
        int idx = tid + i * NT;
        int half = idx >> 9, r = (idx >> 3) & 63, c = idx & 7;
        CP16(sq + (uint32_t)(half * OFF_QLO + r * PADB + c * 16),
             (half ? gQlo : gQhi) + qbase + (size_t)r * DKD + c * 8);
    }
    #pragma unroll
    for (int i = 0; i < 8; i++) {
        int idx = tid + i * NT;
        int half = idx >> 10, r = (idx >> 3) & 127, c = idx & 7;
        CP16(sk + (uint32_t)(half * 18432 + r * PADB + c * 16),
             (half ? gKlo : gKhi) + kbase + (size_t)r * DKD + c * 8);
    }
    asm volatile("cp.async.commit_group;" ::: "memory");
    // ---- group 1: K tile 1 ----
    #pragma unroll
    for (int i = 0; i < 8; i++) {
        int idx = tid + i * NT;
        int half = idx >> 10, r = (idx >> 3) & 127, c = idx & 7;
        CP16(sk + (uint32_t)(KSTAGE + half * 18432 + r * PADB + c * 16),
             (half ? gKlo : gKhi) + kbase + (size_t)(128 + r) * DKD + c * 8);
    }
    asm volatile("cp.async.commit_group;" ::: "memory");

    const uint32_t aHi = sq + (uint32_t)((wq * 16 + (lane & 15)) * PADB + (lane >> 4) * 16);
    const uint32_t aLo = aHi + OFF_QLO;
    const int rowB = wk * 64 + (lane & 7) + (lane >> 4) * 8;
    const uint32_t bBase = sk + (uint32_t)(rowB * PADB + ((lane >> 3) & 1) * 16);

    const int r0l = wq * 16 + (lane >> 2);
    // packed-mask pointers: 16 bytes per (row, tile): offset wk*64 + e*16
    const uint8_t* mp0 = Mb + (size_t)r0l * SSEQ + wk * 64 + (lane & 3) * 16;
    const uint8_t* mp8 = mp0 + 8 * SSEQ;
    float sumE0 = 0.0f, sumE1 = 0.0f;

    for (int t = 0; t < SSEQ / 128; t++) {
        const int kt = t * 128;
        asm volatile("cp.async.wait_group 1;" ::: "memory");
        __syncthreads();

        const uint32_t bHi = bBase + (uint32_t)((t & 1) * KSTAGE);
        const uint32_t bLo = bHi + 18432;

        float acc[8][4];
        #pragma unroll
        for (int n = 0; n < 8; n++)
            #pragma unroll
            for (int j = 0; j < 4; j++) acc[n][j] = 0.0f;

        #pragma unroll
        for (int s = 0; s < 4; s++) {
            uint32_t ah0, ah1, ah2, ah3, al0, al1, al2, al3;
            LDSM4(ah0, ah1, ah2, ah3, aHi + s * 32);
            LDSM4(al0, al1, al2, al3, aLo + s * 32);
            #pragma unroll
            for (int p = 0; p < 4; p++) {
                uint32_t bh0, bh1, bh2, bh3, bl0, bl1, bl2, bl3;
                LDSM4(bh0, bh1, bh2, bh3, bHi + (uint32_t)(p * 16 * PADB + s * 32));
                LDSM4(bl0, bl1, bl2, bl3, bLo + (uint32_t)(p * 16 * PADB + s * 32));
                mma_bf16(acc[2 * p],     ah0, ah1, ah2, ah3, bh0, bh1);
                mma_bf16(acc[2 * p],     ah0, ah1, ah2, ah3, bl0, bl1);
                mma_bf16(acc[2 * p],     al0, al1, al2, al3, bh0, bh1);
                mma_bf16(acc[2 * p + 1], ah0, ah1, ah2, ah3, bh2, bh3);
                mma_bf16(acc[2 * p + 1], ah0, ah1, ah2, ah3, bl2, bl3);
                mma_bf16(acc[2 * p + 1], al0, al1, al2, al3, bh2, bh3);
            }
        }
        __syncthreads();

        // ---- prefetch tile t+2 ----
        if (t + 2 < SSEQ / 128) {
            #pragma unroll
            for (int i = 0; i < 8; i++) {
                int idx = tid + i * NT;
                int half = idx >> 10, r = (idx >> 3) & 127, c = idx & 7;
                CP16(sk + (uint32_t)((t & 1) * KSTAGE + half * 18432 + r * PADB + c * 16),
                     (half ? gKlo : gKhi) + kbase + (size_t)(kt + 256 + r) * DKD + c * 8);
            }
        }
        asm volatile("cp.async.commit_group;" ::: "memory");

        // ---- epilogue: packed mask (1 LDG.128 per row), write scores, exp sums ----
        uint4 mA = *reinterpret_cast<const uint4*>(mp0 + kt);
        uint4 mB = *reinterpret_cast<const uint4*>(mp8 + kt);
        const uint32_t* wa = reinterpret_cast<const uint32_t*>(&mA);
        const uint32_t* wb = reinterpret_cast<const uint32_t*>(&mB);
        #pragma unroll
        for (int nt = 0; nt < 8; nt++) {
            uint32_t ma = wa[nt >> 1] >> ((nt & 1) * 16);
            uint32_t mb = wb[nt >> 1] >> ((nt & 1) * 16);
            float s0 = (ma & 0xFFu)   ? acc[nt][0] : NEGV;
            float s1 = (ma & 0xFF00u) ? acc[nt][1] : NEGV;
            float s2 = (mb & 0xFFu)   ? acc[nt][2] : NEGV;
            float s3 = (mb & 0xFF00u) ? acc[nt][3] : NEGV;
            sumE0 += __expf(s0) + __expf(s1);
            sumE1 += __expf(s2) + __expf(s3);
            int kc = kt + wk * 64 + nt * 8 + 2 * (lane & 3);
            *reinterpret_cast<float2*>(Sp + (size_t)r0l * SSEQ + kc)       = make_float2(s0, s1);
            *reinterpret_cast<float2*>(Sp + (size_t)(r0l + 8) * SSEQ + kc) = make_float2(s2, s3);
        }
    }

    // ---- row-sum reduce ----
    sumE0 += __shfl_xor_sync(0xFFFFFFFFu, sumE0, 1);
    sumE0 += __shfl_xor_sync(0xFFFFFFFFu, sumE0, 2);
    sumE1 += __shfl_xor_sync(0xFFFFFFFFu, sumE1, 1);
    sumE1 += __shfl_xor_sync(0xFFFFFFFFu, sumE1, 2);
    if ((lane & 3) == 0) {
        sred[wk * 64 + r0l]     = sumE0;
        sred[wk * 64 + r0l + 8] = sumE1;
    }
    __syncthreads();
    if (tid < 64) sinv[tid] = 1.0f / (sred[tid] + sred[64 + tid]);
    __syncthreads();

    // ---- fused attn pass: re-read scores (L2-hot), normalize ----
    #pragma unroll 8
    for (int i = 0; i < 64; i++) {
        int idx = tid + i * NT;
        float inv = sinv[idx >> 8];
        float4 s = reinterpret_cast<const float4*>(Sp)[idx];
        float4 a;
        a.x = __expf(s.x) * inv;
        a.y = __expf(s.y) * inv;
        a.z = __expf(s.z) * inv;
        a.w = __expf(s.w) * inv;
        reinterpret_cast<float4*>(Ap)[idx] = a;
    }
}

extern "C" void kernel_launch(void* const* d_in, const int* in_sizes, int n_in,
                              void* d_out, int out_size)
{
    const float* Q = (const float*)d_in[0];
    const float* K = (const float*)d_in[1];
    const int*   M = (const int*)d_in[3];    // d_in[2] = value, unused by outputs

    float* attn   = (float*)d_out;
    float* scores = (float*)d_out + (size_t)BB * HH * SSEQ * SSEQ;

    prep_kernel<<<CVT_BLOCKS + MSK_BLOCKS, 256>>>(Q, K, M);

    cudaFuncSetAttribute(mha_fused, cudaFuncAttributeMaxDynamicSharedMemorySize, SMEM_TOTAL);
    dim3 grid(SSEQ / TQ, HH, BB);
    mha_fused<<<grid, NT, SMEM_TOTAL>>>(attn, scores);
}

// round 9
// speedup vs baseline: 1.1520x; 1.0261x over previous
#include <cuda_runtime.h>
#include <cuda_bf16.h>
#include <math.h>
#include <stdint.h>

#define BB 4
#define HH 16
#define SSEQ 1024
#define DKD 64
#define TQ 128
#define NT 512
#define NEGV (-1.0e9f)
#define PADB 144

#define OFF_QHI 0
#define OFF_QLO 18432
#define OFF_K   36864
#define KSTAGE  36864
#define OFF_RED (OFF_K + 2 * KSTAGE)              // 110592
#define SMEM_TOTAL (OFF_RED + (256 + 128) * 4)    // 112128 -> 2 CTAs/SM

#define NELEM (BB * HH * SSEQ * DKD)
#define NMASK (BB * SSEQ * SSEQ)
#define CVT_BLOCKS ((2 * NELEM / 4) / 256)
#define MSK_BLOCKS ((NMASK / 16) / 256)

__device__ __nv_bfloat16 gQhi[NELEM];
__device__ __nv_bfloat16 gQlo[NELEM];
__device__ __nv_bfloat16 gKhi[NELEM];
__device__ __nv_bfloat16 gKlo[NELEM];
__device__ __align__(16) uint8_t gMB[NMASK];

__device__ __forceinline__ uint32_t smem_u32(const void* p) {
    uint32_t a;
    asm("{ .reg .u64 t; cvta.to.shared.u64 t, %1; cvt.u32.u64 %0, t; }" : "=r"(a) : "l"(p));
    return a;
}
__device__ __forceinline__ uint32_t pack_bf2(__nv_bfloat16 a, __nv_bfloat16 b) {
    return (uint32_t)__bfloat16_as_ushort(a) | ((uint32_t)__bfloat16_as_ushort(b) << 16);
}
__device__ __forceinline__ void mma_bf16(float* d,
                                         uint32_t a0, uint32_t a1, uint32_t a2, uint32_t a3,
                                         uint32_t b0, uint32_t b1) {
    asm volatile(
        "mma.sync.aligned.m16n8k16.row.col.f32.bf16.bf16.f32 "
        "{%0,%1,%2,%3}, {%4,%5,%6,%7}, {%8,%9}, {%0,%1,%2,%3};"
        : "+f"(d[0]), "+f"(d[1]), "+f"(d[2]), "+f"(d[3])
        : "r"(a0), "r"(a1), "r"(a2), "r"(a3), "r"(b0), "r"(b1));
}
#define LDSM4(r0, r1, r2, r3, a) \
    asm volatile("ldmatrix.sync.aligned.m8n8.x4.shared.b16 {%0,%1,%2,%3}, [%4];" \
                 : "=r"(r0), "=r"(r1), "=r"(r2), "=r"(r3) : "r"(a))
#define CP16(dst, src) \
    asm volatile("cp.async.cg.shared.global [%0], [%1], 16;" :: "r"(dst), "l"(src) : "memory")

// ---- combined pre-pass: bf16 hi/lo conversion + mask byte-packing ----
__global__ void __launch_bounds__(256, 8)
prep_kernel(const float* __restrict__ Q, const float* __restrict__ K,
            const int* __restrict__ M)
{
    if (blockIdx.x < CVT_BLOCKS) {
        size_t i = (size_t)blockIdx.x * 256 + threadIdx.x;
        bool isQ = i < (NELEM / 4);
        size_t j = isQ ? i : i - (NELEM / 4);
        float4 v = reinterpret_cast<const float4*>(isQ ? Q : K)[j];
        if (isQ) { v.x *= 0.125f; v.y *= 0.125f; v.z *= 0.125f; v.w *= 0.125f; }
        __nv_bfloat16 bx = __float2bfloat16_rn(v.x), by = __float2bfloat16_rn(v.y);
        __nv_bfloat16 bz = __float2bfloat16_rn(v.z), bw = __float2bfloat16_rn(v.w);
        uint2 hi = make_uint2(pack_bf2(bx, by), pack_bf2(bz, bw));
        uint2 lo = make_uint2(
            pack_bf2(__float2bfloat16_rn(v.x - __bfloat162float(bx)),
                     __float2bfloat16_rn(v.y - __bfloat162float(by))),
            pack_bf2(__float2bfloat16_rn(v.z - __bfloat162float(bz)),
                     __float2bfloat16_rn(v.w - __bfloat162float(bw))));
        if (isQ) { reinterpret_cast<uint2*>(gQhi)[j] = hi; reinterpret_cast<uint2*>(gQlo)[j] = lo; }
        else     { reinterpret_cast<uint2*>(gKhi)[j] = hi; reinterpret_cast<uint2*>(gKlo)[j] = lo; }
    } else {
        int t = (blockIdx.x - CVT_BLOCKS) * 256 + threadIdx.x;
        int tile = t >> 3;
        int w = t & 7;
        int half = w >> 2, e = w & 3;
        const int* src = M + (size_t)tile * 128 + half * 64 + 2 * e;
        uint32_t words[4];
        #pragma unroll
        for (int p = 0; p < 4; p++) {
            int2 v0 = *reinterpret_cast<const int2*>(src + (2 * p) * 8);
            int2 v1 = *reinterpret_cast<const int2*>(src + (2 * p + 1) * 8);
            words[p] = (v0.x ? 1u : 0u) | (v0.y ? 0x100u : 0u)
                     | (v1.x ? 0x10000u : 0u) | (v1.y ? 0x1000000u : 0u);
        }
        *reinterpret_cast<uint4*>(gMB + (size_t)tile * 128 + w * 16) =
            make_uint4(words[0], words[1], words[2], words[3]);
    }
}

__global__ void __launch_bounds__(NT, 2)
mha_fused(float* __restrict__ attn, float* __restrict__ scores)
{
    extern __shared__ char sm[];
    float* sred = (float*)(sm + OFF_RED);   // [256]
    float* sinv = sred + 256;               // [128]

    const int tid  = threadIdx.x;
    const int lane = tid & 31;
    const int wid  = tid >> 5;              // 0..15
    const int wq   = wid >> 1;              // 0..7 : 16-row q subtile
    const int wk   = wid & 1;               // 0..1 : 64-col k half
    const int qt = blockIdx.x, h = blockIdx.y, b = blockIdx.z;
    const int q0 = qt * TQ;

    const size_t qbase = ((size_t)(b * HH + h) * SSEQ + q0) * DKD;
    const size_t kbase = (size_t)(b * HH + h) * SSEQ * DKD;
    const uint8_t* Mb = gMB + ((size_t)b * SSEQ + q0) * SSEQ;
    float* Sp = scores + ((size_t)(b * HH + h) * SSEQ + q0) * SSEQ;
    float* Ap = attn   + ((size_t)(b * HH + h) * SSEQ + q0) * SSEQ;

    const uint32_t sq = smem_u32(sm);
    const uint32_t sk = sq + OFF_K;

    // ---- prologue group 0: Q (128 rows, hi+lo: 2048 chunks) + K tile 0 ----
    #pragma unroll
    for (int i = 0; i < 4; i++) {
        int idx = tid + i * NT;
        int half = idx >> 10, r = (idx >> 3) & 127, c = idx & 7;
        CP16(sq + (uint32_t)(half * OFF_QLO + r * PADB + c * 16),
             (half ? gQlo : gQhi) + qbase + (size_t)r * DKD + c * 8);
    }
    #pragma unroll
    for (int i = 0; i < 4; i++) {
        int idx = tid + i * NT;
        int half = idx >> 10, r = (idx >> 3) & 127, c = idx & 7;
        CP16(sk + (uint32_t)(half * 18432 + r * PADB + c * 16),
             (half ? gKlo : gKhi) + kbase + (size_t)r * DKD + c * 8);
    }
    asm volatile("cp.async.commit_group;" ::: "memory");
    // ---- group 1: K tile 1 ----
    #pragma unroll
    for (int i = 0; i < 4; i++) {
        int idx = tid + i * NT;
        int half = idx >> 10, r = (idx >> 3) & 127, c = idx & 7;
        CP16(sk + (uint32_t)(KSTAGE + half * 18432 + r * PADB + c * 16),
             (half ? gKlo : gKhi) + kbase + (size_t)(128 + r) * DKD + c * 8);
    }
    asm volatile("cp.async.commit_group;" ::: "memory");

    const uint32_t aHi = sq + (uint32_t)((wq * 16 + (lane & 15)) * PADB + (lane >> 4) * 16);
    const uint32_t aLo = aHi + OFF_QLO;
    const int rowB = wk * 64 + (lane & 7) + (lane >> 4) * 8;
    const uint32_t bBase = sk + (uint32_t)(rowB * PADB + ((lane >> 3) & 1) * 16);

    const int r0l = wq * 16 + (lane >> 2);
    const uint8_t* mp0 = Mb + (size_t)r0l * SSEQ + wk * 64 + (lane & 3) * 16;
    const uint8_t* mp8 = mp0 + 8 * SSEQ;
    float sumE0 = 0.0f, sumE1 = 0.0f;

    for (int t = 0; t < SSEQ / 128; t++) {
        const int kt = t * 128;
        asm volatile("cp.async.wait_group 1;" ::: "memory");
        __syncthreads();

        const uint32_t bHi = bBase + (uint32_t)((t & 1) * KSTAGE);
        const uint32_t bLo = bHi + 18432;

        float acc[8][4];
        #pragma unroll
        for (int n = 0; n < 8; n++)
            #pragma unroll
            for (int j = 0; j < 4; j++) acc[n][j] = 0.0f;

        #pragma unroll
        for (int s = 0; s < 4; s++) {
            uint32_t ah0, ah1, ah2, ah3, al0, al1, al2, al3;
            LDSM4(ah0, ah1, ah2, ah3, aHi + s * 32);
            LDSM4(al0, al1, al2, al3, aLo + s * 32);
            #pragma unroll
            for (int p = 0; p < 4; p++) {
                uint32_t bh0, bh1, bh2, bh3, bl0, bl1, bl2, bl3;
                LDSM4(bh0, bh1, bh2, bh3, bHi + (uint32_t)(p * 16 * PADB + s * 32));
                LDSM4(bl0, bl1, bl2, bl3, bLo + (uint32_t)(p * 16 * PADB + s * 32));
                mma_bf16(acc[2 * p],     ah0, ah1, ah2, ah3, bh0, bh1);
                mma_bf16(acc[2 * p],     ah0, ah1, ah2, ah3, bl0, bl1);
                mma_bf16(acc[2 * p],     al0, al1, al2, al3, bh0, bh1);
                mma_bf16(acc[2 * p + 1], ah0, ah1, ah2, ah3, bh2, bh3);
                mma_bf16(acc[2 * p + 1], ah0, ah1, ah2, ah3, bl2, bl3);
                mma_bf16(acc[2 * p + 1], al0, al1, al2, al3, bh2, bh3);
            }
        }
        __syncthreads();

        // ---- prefetch tile t+2 into stage t&1 ----
        if (t + 2 < SSEQ / 128) {
            #pragma unroll
            for (int i = 0; i < 4; i++) {
                int idx = tid + i * NT;
                int half = idx >> 10, r = (idx >> 3) & 127, c = idx & 7;
                CP16(sk + (uint32_t)((t & 1) * KSTAGE + half * 18432 + r * PADB + c * 16),
                     (half ? gKlo : gKhi) + kbase + (size_t)(kt + 256 + r) * DKD + c * 8);
            }
        }
        asm volatile("cp.async.commit_group;" ::: "memory");

        // ---- epilogue: packed mask, write scores, exp sums ----
        uint4 mA = *reinterpret_cast<const uint4*>(mp0 + kt);
        uint4 mB = *reinterpret_cast<const uint4*>(mp8 + kt);
        const uint32_t* wa = reinterpret_cast<const uint32_t*>(&mA);
        const uint32_t* wb = reinterpret_cast<const uint32_t*>(&mB);
        #pragma unroll
        for (int nt = 0; nt < 8; nt++) {
            uint32_t ma = wa[nt >> 1] >> ((nt & 1) * 16);
            uint32_t mb = wb[nt >> 1] >> ((nt & 1) * 16);
            float s0 = (ma & 0xFFu)   ? acc[nt][0] : NEGV;
            float s1 = (ma & 0xFF00u) ? acc[nt][1] : NEGV;
            float s2 = (mb & 0xFFu)   ? acc[nt][2] : NEGV;
            float s3 = (mb & 0xFF00u) ? acc[nt][3] : NEGV;
            sumE0 += __expf(s0) + __expf(s1);
            sumE1 += __expf(s2) + __expf(s3);
            int kc = kt + wk * 64 + nt * 8 + 2 * (lane & 3);
            *reinterpret_cast<float2*>(Sp + (size_t)r0l * SSEQ + kc)       = make_float2(s0, s1);
            *reinterpret_cast<float2*>(Sp + (size_t)(r0l + 8) * SSEQ + kc) = make_float2(s2, s3);
        }
    }

    // ---- row-sum reduce ----
    sumE0 += __shfl_xor_sync(0xFFFFFFFFu, sumE0, 1);
    sumE0 += __shfl_xor_sync(0xFFFFFFFFu, sumE0, 2);
    sumE1 += __shfl_xor_sync(0xFFFFFFFFu, sumE1, 1);
    sumE1 += __shfl_xor_sync(0xFFFFFFFFu, sumE1, 2);
    if ((lane & 3) == 0) {
        sred[wk * 128 + r0l]     = sumE0;
        sred[wk * 128 + r0l + 8] = sumE1;
    }
    __syncthreads();
    if (tid < 128) sinv[tid] = 1.0f / (sred[tid] + sred[128 + tid]);
    __syncthreads();

    // ---- fused attn pass: re-read scores (L2-hot), normalize ----
    #pragma unroll 8
    for (int i = 0; i < 64; i++) {
        int idx = tid + i * NT;                 // 32768 float4 = 128 rows x 256
        float inv = sinv[idx >> 8];
        float4 s = reinterpret_cast<const float4*>(Sp)[idx];
        float4 a;
        a.x = __expf(s.x) * inv;
        a.y = __expf(s.y) * inv;
        a.z = __expf(s.z) * inv;
        a.w = __expf(s.w) * inv;
        reinterpret_cast<float4*>(Ap)[idx] = a;
    }
}

extern "C" void kernel_launch(void* const* d_in, const int* in_sizes, int n_in,
                              void* d_out, int out_size)
{
    const float* Q = (const float*)d_in[0];
    const float* K = (const float*)d_in[1];
    const int*   M = (const int*)d_in[3];    // d_in[2] = value, unused by outputs

    float* attn   = (float*)d_out;
    float* scores = (float*)d_out + (size_t)BB * HH * SSEQ * SSEQ;

    prep_kernel<<<CVT_BLOCKS + MSK_BLOCKS, 256>>>(Q, K, M);

    cudaFuncSetAttribute(mha_fused, cudaFuncAttributeMaxDynamicSharedMemorySize, SMEM_TOTAL);
    dim3 grid(SSEQ / TQ, HH, BB);            // (8,16,4) = 512 CTAs
    mha_fused<<<grid, NT, SMEM_TOTAL>>>(attn, scores);
}